// round 9
// baseline (speedup 1.0000x reference)
#include <cuda_runtime.h>
#include <cuda_bf16.h>
#include <cstdint>

// Dequant: out[r][c] = (float)q[r][c] * row_stats[r] * (1/127)
// ROWS = COLS = 8192, int32 in -> fp32 out. Pure streaming: 512 MiB total.
//
// R9: PERSISTENT single-wave variant of the measured-best R3/R6 config.
// Grid = 912 CTAs (152 SMs x 6 resident CTAs) -> exactly one wave, zero
// wave transitions; each CTA grid-strides over ~9 rows, so the per-CTA
// load-pipeline ramp (first-load DRAM latency) is paid 912x instead of 8192x.
// Per row: uniform scale (one __ldg), 8 front-batched LDG.E.128 (MLP=8),
// 8 STG.E.128, .cs streaming hints both directions (measured best).

#define VPT 8                         // int4 vectors per thread
#define TPB 256                       // TPB*VPT = 2048 vecs = 8192 cols = 1 row
#define GRID 912                      // 152 SMs x 6 CTAs = one full wave

__global__ void __launch_bounds__(TPB, 6)
dequant_kernel(const int4* __restrict__ q,
               const float* __restrict__ row_stats,
               float4* __restrict__ out,
               int rows)
{
    for (int row = blockIdx.x; row < rows; row += GRID) {
        const float scale = __ldg(&row_stats[row]) * (1.0f / 127.0f);
        const int base = row * (TPB * VPT) + threadIdx.x;

        int4 v[VPT];
#pragma unroll
        for (int j = 0; j < VPT; j++)
            v[j] = __ldcs(&q[base + j * TPB]);

#pragma unroll
        for (int j = 0; j < VPT; j++) {
            float4 r;
            r.x = (float)v[j].x * scale;
            r.y = (float)v[j].y * scale;
            r.z = (float)v[j].z * scale;
            r.w = (float)v[j].w * scale;
            __stcs(&out[base + j * TPB], r);
        }
    }
}

extern "C" void kernel_launch(void* const* d_in, const int* in_sizes, int n_in,
                              void* d_out, int out_size)
{
    const int4*  q         = (const int4*)d_in[0];   // int32 [8192,8192]
    const float* row_stats = (const float*)d_in[1];  // fp32  [8192]
    float4*      out       = (float4*)d_out;

    const int rows = in_sizes[1];                    // 8192

    dequant_kernel<<<GRID, TPB>>>(q, row_stats, out, rows);
}

// round 10
// speedup vs baseline: 1.1004x; 1.1004x over previous
#include <cuda_runtime.h>
#include <cuda_bf16.h>
#include <cstdint>

// Dequant: out[r][c] = (float)q[r][c] * row_stats[r] * (1/127)
// ROWS = COLS = 8192, int32 in -> fp32 out. Pure streaming: 512 MiB total.
//
// FINAL — measured-best config, reproduced 4x (R3/R6/R8: 73.9-74.8us kernel,
// 82.0us end-to-end). Full sweep results (kernel us):
//   VPT:      1 -> 82.5 | 4 -> 74.5 | 8 -> 73.9  (saturates)
//   stores:   .cs 73.9 | .wt 75.3 | default 75.5
//   layout:   4KB-strided 73.9 | contiguous-per-warp 75.2
//   grid:     oversubscribed 8192 CTAs 73.9 | persistent 912 CTAs 78.9
//             (oversubscription is the latency hider: persistent loop kills
//              MLP at every row seam; wave transitions overlap for free)
// Config: one block == one row (256 thr x 8 int4 = 8192 cols), uniform
// per-block scale, 8 front-batched LDG.E.128 (MLP=8), .cs both directions.
// Sits at 81-82% DRAM-active (~6.45 TB/s) = B300 mixed 1:1 read/write
// HBM-stream ceiling; traffic is fixed by the I/O contract. Roofline reached.

#define VPT 8                         // int4 vectors per thread
#define TPB 256                       // TPB*VPT = 2048 vecs = 8192 cols = 1 row

__global__ void __launch_bounds__(TPB, 6)
dequant_kernel(const int4* __restrict__ q,
               const float* __restrict__ row_stats,
               float4* __restrict__ out)
{
    // Uniform per-block scale: block r handles row r.
    const float scale = __ldg(&row_stats[blockIdx.x]) * (1.0f / 127.0f);

    const int base = blockIdx.x * (TPB * VPT) + threadIdx.x;

    // Front-batch 8 independent LDG.E.128 (MLP=8), streaming hint.
    int4 v[VPT];
#pragma unroll
    for (int j = 0; j < VPT; j++)
        v[j] = __ldcs(&q[base + j * TPB]);

#pragma unroll
    for (int j = 0; j < VPT; j++) {
        float4 r;
        r.x = (float)v[j].x * scale;
        r.y = (float)v[j].y * scale;
        r.z = (float)v[j].z * scale;
        r.w = (float)v[j].w * scale;
        __stcs(&out[base + j * TPB], r);   // streaming store (measured best)
    }
}

extern "C" void kernel_launch(void* const* d_in, const int* in_sizes, int n_in,
                              void* d_out, int out_size)
{
    const int4*  q         = (const int4*)d_in[0];   // int32 [8192,8192]
    const float* row_stats = (const float*)d_in[1];  // fp32  [8192]
    float4*      out       = (float4*)d_out;

    const int rows = in_sizes[1];                    // 8192 blocks, one per row

    dequant_kernel<<<rows, TPB>>>(q, row_stats, out);
}